// round 13
// baseline (speedup 1.0000x reference)
#include <cuda_runtime.h>
#include <math.h>

#define NMAT 256
#define D 64
#define DD 4096          // 64*64
#define DQ 68            // padded row stride (float4-aligned)
#define NSWEEP_OS 7      // one-sided Jacobi sweeps (6 fails @1.9e-3, 8 proven 1.3e-5)

// ---------------- device scratch (no allocations allowed) ----------------
__device__ float g_L[NMAT * DD];          // log(X) matrices        (4 MB)
__device__ float g_S[NMAT * DD];          // log(X) + M             (4 MB)
__device__ float g_gp[8 * NMAT * NMAT];   // split-K gram partials  (2 MB)
__device__ float g_W[NMAT * NMAT];        // kernel weights         (256 KB)
__device__ float g_sq[NMAT];
__device__ float g_s[NMAT];
__device__ float g_rs[NMAT];              // row sums
__device__ float g_cs[NMAT];              // col sums

// ========================================================================
// Kernel 1: one-sided Jacobi log, TWO matrices per 128-thread CTA
//   (warp pair (0,1) -> matrix 2bx, pair (2,3) -> matrix 2bx+1), so the
//   CTA's 4 warps cover all 4 SMSPs (wid%4 mapping). Within a pair, lane l
//   of half h holds elements [32h,32h+32) of column pair (2l,2l+1).
//   Tangent-form rotations, division/branch-free chain. Cross-half dot via
//   double-buffered smem + NAMED barrier (pair-private, id 1+p).
//   At convergence true columns are lambda_i*v_i:
//   log X = sum_i (log l_i / l_i^2) g_i g_i^T.
// ========================================================================
__global__ __launch_bounds__(128) void onesided_log_kernel(const float* __restrict__ X) {
    __shared__ float Gsm[2][D * DQ];       // per-pair columns (Gsm[p][elem*DQ+col])
    __shared__ float wcol[2][D];           // per-column log-weights
    __shared__ float pdot[2][2][2][32];    // [pair][buf][half][lane]
    __shared__ float2 pnorm[2][2][32];     // [pair][half][lane]
    __shared__ float reds[2][2], redq[2][2];

    const int tid  = threadIdx.x;
    const int w    = tid >> 5;
    const int p    = w >> 1;               // pair = matrix slot in CTA
    const int h    = w & 1;                // element half
    const int ow   = h ^ 1;
    const int lane = tid & 31;
    const int m    = 2 * blockIdx.x + p;
    const int barid = 1 + p;
    const unsigned FULL = 0xffffffffu;
    const float* Xm = X + (size_t)m * DD;

#define PAIR_BAR() asm volatile("bar.sync %0, 64;" :: "r"(barid) : "memory")

    float a[32], b[32];

    // X symmetric: column c == row c. Each half loads its element range.
    {
        const float4* ra = (const float4*)(Xm + (2 * lane)     * D + 32 * h);
        const float4* rb = (const float4*)(Xm + (2 * lane + 1) * D + 32 * h);
        #pragma unroll
        for (int t = 0; t < 8; ++t) {
            float4 v = ra[t];
            a[4*t+0] = v.x; a[4*t+1] = v.y; a[4*t+2] = v.z; a[4*t+3] = v.w;
            float4 u = rb[t];
            b[4*t+0] = u.x; b[4*t+1] = u.y; b[4*t+2] = u.z; b[4*t+3] = u.w;
        }
    }

    // initial full norms via partial exchange
    float na, nb, sa = 1.0f, sb = 1.0f, isa = 1.0f, isb = 1.0f;
    {
        float n0 = 0.f, n1 = 0.f, m0 = 0.f, m1 = 0.f;
        #pragma unroll
        for (int k = 0; k < 32; k += 2) {
            n0 = fmaf(a[k], a[k], n0);     n1 = fmaf(a[k+1], a[k+1], n1);
            m0 = fmaf(b[k], b[k], m0);     m1 = fmaf(b[k+1], b[k+1], m1);
        }
        float pa = n0 + n1, pb2 = m0 + m1;
        pnorm[p][h][lane] = make_float2(pa, pb2);
        PAIR_BAR();
        float2 o = pnorm[p][ow][lane];
        na = pa + o.x;            // commutative -> identical in both halves
        nb = pb2 + o.y;
    }

    int pb = 0;
    for (int sw = 0; sw < NSWEEP_OS; ++sw) {
        for (int rr = 0; rr < 63; ++rr) {
            // partial cross dot (2-way ILP)
            float g0 = 0.f, g1 = 0.f;
            #pragma unroll
            for (int k = 0; k < 32; k += 2) {
                g0 = fmaf(a[k+0], b[k+0], g0);
                g1 = fmaf(a[k+1], b[k+1], g1);
            }
            float gp = g0 + g1;
            pdot[p][pb][h][lane] = gp;
            PAIR_BAR();
            float ghat = gp + pdot[p][pb][ow][lane];   // commutative sum
            pb ^= 1;

            float gam = sa * sb * ghat;                // true gamma

            // branch-free rotation params (gam==0 -> t ~ 5e-19 -> no-op)
            float tau = (nb - na) * __fdividef(0.5f, gam);
            tau = fminf(fmaxf(tau, -1e18f), 1e18f);    // NaN-safe clamp
            float opt2 = fmaf(tau, tau, 1.0f);
            float sq   = opt2 * rsqrtf(opt2);          // sqrt(1+tau^2)
            float tt   = copysignf(__fdividef(1.0f, fabsf(tau) + sq), tau);
            float c2   = fmaf(tt, tt, 1.0f);
            float c    = rsqrtf(c2);
            float ic   = c2 * c;                       // exactly 1/c
            float s    = tt * c;

            float u = tt * sb * isa;                   // a' = a - u*b
            float v = tt * sa * isb;                   // b' = b + v*a

            #pragma unroll
            for (int k = 0; k < 32; ++k) {
                float av = a[k], bv = b[k];
                a[k] = fmaf(-u, bv, av);
                b[k] = fmaf( v, av, bv);
            }
            sa *= c; sb *= c; isa *= ic; isb *= ic;

            // true-norm tracking (exact rotation identities)
            float csg = 2.0f * c * s * gam;
            float cc2 = c * c, ss2 = s * s;
            float na_n = cc2 * na + ss2 * nb - csg;
            float nb_n = ss2 * na + cc2 * nb + csg;
            na = na_n; nb = nb_n;

            // Brent-Luk permutation (within each warp; identical patterns)
            {
                float tn, up, dn, o;
                o = na; tn = (lane == 0) ? nb : na;
                up = __shfl_up_sync(FULL, tn, 1);
                dn = __shfl_down_sync(FULL, nb, 1);
                na = (lane == 0)  ? o : up;
                nb = (lane == 31) ? o : dn;

                o = sa; tn = (lane == 0) ? sb : sa;
                up = __shfl_up_sync(FULL, tn, 1);
                dn = __shfl_down_sync(FULL, sb, 1);
                sa = (lane == 0)  ? o : up;
                sb = (lane == 31) ? o : dn;

                o = isa; tn = (lane == 0) ? isb : isa;
                up = __shfl_up_sync(FULL, tn, 1);
                dn = __shfl_down_sync(FULL, isb, 1);
                isa = (lane == 0)  ? o : up;
                isb = (lane == 31) ? o : dn;
            }
            #pragma unroll
            for (int k = 0; k < 32; ++k) {
                float oa  = a[k];
                float tmp = (lane == 0) ? b[k] : oa;
                float up  = __shfl_up_sync(FULL, tmp, 1);
                float dn  = __shfl_down_sync(FULL, b[k], 1);
                a[k] = (lane == 0)  ? oa : up;
                b[k] = (lane == 31) ? oa : dn;
            }
        }

        // per-sweep renormalization (scales replicated across halves)
        #pragma unroll
        for (int k = 0; k < 32; ++k) { a[k] *= sa; b[k] *= sb; }
        sa = 1.0f; sb = 1.0f; isa = 1.0f; isb = 1.0f;
    }

    // exact final norms via partial exchange
    {
        float n0 = 0.f, n1 = 0.f, m0 = 0.f, m1 = 0.f;
        #pragma unroll
        for (int k = 0; k < 32; k += 2) {
            n0 = fmaf(a[k], a[k], n0);     n1 = fmaf(a[k+1], a[k+1], n1);
            m0 = fmaf(b[k], b[k], m0);     m1 = fmaf(b[k+1], b[k+1], m1);
        }
        float pa = n0 + n1, pb2 = m0 + m1;
        pnorm[p][h][lane] = make_float2(pa, pb2);
        PAIR_BAR();
        float2 o = pnorm[p][ow][lane];
        na = pa + o.x; nb = pb2 + o.y;
    }

    // weight = log(lambda)/lambda^2 with lambda^2 = |g|^2
    float wa = 0.5f * logf(fmaxf(na, 1e-30f)) / na;
    float wb = 0.5f * logf(fmaxf(nb, 1e-30f)) / nb;

    // stash columns + per-column weights (both halves write same wcol value)
    {
        const int ia = 2 * lane, ib = 2 * lane + 1;
        #pragma unroll
        for (int k = 0; k < 32; ++k) {
            int r = 32 * h + k;
            Gsm[p][r * DQ + ia] = a[k];
            Gsm[p][r * DQ + ib] = b[k];
        }
        if (h == 0) { wcol[p][ia] = wa; wcol[p][ib] = wb; }
    }
    __syncthreads();

    // L[r,c] = sum_col wcol[col]*G[r,col]*G[c,col]; thread -> (matrix rp, row r)
    const int rp = tid >> 6;       // matrix slot (uniform per warp)
    const int r  = tid & 63;
    const int m2 = 2 * blockIdx.x + rp;

    float hrow[64];
    #pragma unroll
    for (int t = 0; t < 16; ++t) {
        float4 g4 = *(const float4*)&Gsm[rp][r * DQ + 4 * t];
        float4 w4 = *(const float4*)&wcol[rp][4 * t];
        hrow[4*t+0] = g4.x * w4.x; hrow[4*t+1] = g4.y * w4.y;
        hrow[4*t+2] = g4.z * w4.z; hrow[4*t+3] = g4.w * w4.w;
    }

    float ssum = 0.f, sqsum = 0.f;
    float* orow = g_L + (size_t)m2 * DD + r * D;
    for (int c4 = 0; c4 < D; c4 += 4) {
        float acc[4] = {0.f, 0.f, 0.f, 0.f};
        #pragma unroll
        for (int cc = 0; cc < 4; ++cc) {
            const int c = c4 + cc;
            #pragma unroll
            for (int t = 0; t < 16; ++t) {
                float4 g = *(const float4*)&Gsm[rp][c * DQ + 4 * t];  // broadcast
                acc[cc] = fmaf(hrow[4*t+0], g.x, acc[cc]);
                acc[cc] = fmaf(hrow[4*t+1], g.y, acc[cc]);
                acc[cc] = fmaf(hrow[4*t+2], g.z, acc[cc]);
                acc[cc] = fmaf(hrow[4*t+3], g.w, acc[cc]);
            }
        }
        *(float4*)&orow[c4] = make_float4(acc[0], acc[1], acc[2], acc[3]);
        #pragma unroll
        for (int cc = 0; cc < 4; ++cc) {
            ssum += acc[cc];
            sqsum = fmaf(acc[cc], acc[cc], sqsum);
        }
    }
    #pragma unroll
    for (int o = 16; o; o >>= 1) {
        ssum  += __shfl_down_sync(FULL, ssum,  o);
        sqsum += __shfl_down_sync(FULL, sqsum, o);
    }
    if (lane == 0) { reds[rp][(tid >> 5) & 1] = ssum; redq[rp][(tid >> 5) & 1] = sqsum; }
    __syncthreads();
    if ((tid & 63) == 0) {
        g_s[m2]  = reds[rp][0] + reds[rp][1];
        g_sq[m2] = redq[rp][0] + redq[rp][1];
    }
#undef PAIR_BAR
}

// ========================================================================
// Kernel 2: gram partials  g_gp[z][i][j] = sum_{k in z-chunk} L[i][k] L[j][k]
// ========================================================================
__global__ __launch_bounds__(256) void gram_kernel() {
    __shared__ float As[64 * 17];
    __shared__ float Bs[64 * 17];
    const int bj = blockIdx.x, bi = blockIdx.y, bz = blockIdx.z;
    const int tid = threadIdx.x;
    const int ty = tid >> 4, tx = tid & 15;

    float acc[4][4];
    #pragma unroll
    for (int r = 0; r < 4; ++r)
        #pragma unroll
        for (int c = 0; c < 4; ++c) acc[r][c] = 0.0f;

    const int k0 = bz * 512;
    for (int kc = 0; kc < 512; kc += 16) {
        for (int l = tid; l < 1024; l += 256) {
            int r = l >> 4, kk = l & 15;
            As[r * 17 + kk] = g_L[(size_t)(bi * 64 + r) * DD + k0 + kc + kk];
            Bs[r * 17 + kk] = g_L[(size_t)(bj * 64 + r) * DD + k0 + kc + kk];
        }
        __syncthreads();
        #pragma unroll
        for (int kk = 0; kk < 16; ++kk) {
            float a[4], b[4];
            #pragma unroll
            for (int r = 0; r < 4; ++r) a[r] = As[(ty * 4 + r) * 17 + kk];
            #pragma unroll
            for (int c = 0; c < 4; ++c) b[c] = Bs[(tx * 4 + c) * 17 + kk];
            #pragma unroll
            for (int r = 0; r < 4; ++r)
                #pragma unroll
                for (int c = 0; c < 4; ++c)
                    acc[r][c] = fmaf(a[r], b[c], acc[r][c]);
        }
        __syncthreads();
    }
    #pragma unroll
    for (int r = 0; r < 4; ++r)
        #pragma unroll
        for (int c = 0; c < 4; ++c)
            g_gp[((size_t)bz * NMAT + bi * 64 + ty * 4 + r) * NMAT + bj * 64 + tx * 4 + c] = acc[r][c];
}

// ========================================================================
// Kernel 3: W = exp(-0.5 * pds / bw^2), fused row sums.  block = row i
// ========================================================================
__global__ __launch_bounds__(256) void w_kernel(const float* __restrict__ bwp) {
    __shared__ float red[8];
    const int i = blockIdx.x;
    const int j = threadIdx.x;

    float g = 0.0f;
    #pragma unroll
    for (int z = 0; z < 8; ++z)
        g += g_gp[((size_t)z * NMAT + i) * NMAT + j];

    const float bw  = bwp[0];
    const float inv = 0.5f / (bw * bw);
    const float eps = 1e-7f;
    float pds = g_sq[i] + g_sq[j] - 2.0f * g
              + 2.0f * eps * (g_s[j] - g_s[i])
              + eps * eps * 4096.0f;
    float wv = expf(-pds * inv);
    g_W[i * NMAT + j] = wv;

    float sum = wv;
    #pragma unroll
    for (int o = 16; o; o >>= 1) sum += __shfl_down_sync(0xffffffffu, sum, o);
    if ((j & 31) == 0) red[j >> 5] = sum;
    __syncthreads();
    if (j == 0) {
        float t = 0.0f;
        #pragma unroll
        for (int w = 0; w < 8; ++w) t += red[w];
        g_rs[i] = t;
    }
}

// col sums: 8 blocks x 256 threads, coalesced
__global__ __launch_bounds__(256) void colsum_kernel() {
    __shared__ float part[8][32];
    const int c0 = blockIdx.x * 32;
    const int c = threadIdx.x & 31;
    const int rchunk = threadIdx.x >> 5;
    float s = 0.0f;
    #pragma unroll
    for (int rr = 0; rr < 32; ++rr)
        s += g_W[(rchunk * 32 + rr) * NMAT + c0 + c];
    part[rchunk][c] = s;
    __syncthreads();
    if (threadIdx.x < 32) {
        float t = 0.0f;
        #pragma unroll
        for (int w = 0; w < 8; ++w) t += part[w][threadIdx.x];
        g_cs[c0 + threadIdx.x] = t;
    }
}

// ========================================================================
// Kernel 4: C = W^T L, fused mean-shift epilogue -> S = L_k + (C - cs_k L_k)/rs_k
// ========================================================================
__global__ __launch_bounds__(256) void ms_kernel() {
    __shared__ float Wt[16 * 65];
    __shared__ float Lt[16 * 65];
    const int bc = blockIdx.x;   // column tile
    const int bk = blockIdx.y;   // k (output row) tile
    const int tid = threadIdx.x;
    const int ty = tid >> 4, tx = tid & 15;

    float acc[4][4];
    #pragma unroll
    for (int r = 0; r < 4; ++r)
        #pragma unroll
        for (int c = 0; c < 4; ++c) acc[r][c] = 0.0f;

    for (int j0 = 0; j0 < NMAT; j0 += 16) {
        for (int l = tid; l < 1024; l += 256) {
            int jj = l >> 6, c = l & 63;
            Wt[jj * 65 + c] = g_W[(j0 + jj) * NMAT + bk * 64 + c];
            Lt[jj * 65 + c] = g_L[(size_t)(j0 + jj) * DD + bc * 64 + c];
        }
        __syncthreads();
        #pragma unroll
        for (int jj = 0; jj < 16; ++jj) {
            float a[4], b[4];
            #pragma unroll
            for (int r = 0; r < 4; ++r) a[r] = Wt[jj * 65 + ty * 4 + r];
            #pragma unroll
            for (int c = 0; c < 4; ++c) b[c] = Lt[jj * 65 + tx * 4 + c];
            #pragma unroll
            for (int r = 0; r < 4; ++r)
                #pragma unroll
                for (int c = 0; c < 4; ++c)
                    acc[r][c] = fmaf(a[r], b[c], acc[r][c]);
        }
        __syncthreads();
    }
    #pragma unroll
    for (int r = 0; r < 4; ++r) {
        int k = bk * 64 + ty * 4 + r;
        float rs = g_rs[k], cs = g_cs[k];
        float inv_rs = 1.0f / rs;
        #pragma unroll
        for (int c = 0; c < 4; ++c) {
            int col = bc * 64 + tx * 4 + c;
            float lk = g_L[(size_t)k * DD + col];
            g_S[(size_t)k * DD + col] = lk + (acc[r][c] - cs * lk) * inv_rs;
        }
    }
}

// ========================================================================
// Kernel 5: expm(S), scaling-and-squaring + order-8 Horner (first step folded
//   into init). 128 threads: 2 threads per row, each owns a 32-column half.
// ========================================================================
__global__ __launch_bounds__(128) void expm_kernel(float* __restrict__ out) {
    __shared__ float Q[D * DQ];
    __shared__ float redw[4];

    const int m   = blockIdx.x;
    const int tid = threadIdx.x;
    const int i   = tid >> 1;          // row
    const int c0  = (tid & 1) * 32;    // column half base

    // full B row straight from gmem (both half-threads load the same row)
    float brow[64];
    {
        const float4* sr = (const float4*)(g_S + (size_t)m * DD + i * D);
        #pragma unroll
        for (int t = 0; t < 16; ++t) {
            float4 v = sr[t];
            brow[4*t+0] = v.x; brow[4*t+1] = v.y;
            brow[4*t+2] = v.z; brow[4*t+3] = v.w;
        }
    }

    // Frobenius norm: each thread contributes its own half's squares (exact cover)
    float local = 0.0f;
    #pragma unroll
    for (int k = 0; k < 32; ++k) local = fmaf(brow[c0 + k], brow[c0 + k], local);
    #pragma unroll
    for (int o = 16; o; o >>= 1) local += __shfl_down_sync(0xffffffffu, local, o);
    if ((tid & 31) == 0) redw[tid >> 5] = local;
    __syncthreads();

    float nf = sqrtf((redw[0] + redw[1]) + (redw[2] + redw[3]));
    int ksc = 0;
    if (nf > 0.5f) {
        ksc = (int)ceilf(log2f(nf * 2.0f));
        if (ksc > 15) ksc = 15;
        if (ksc < 0)  ksc = 0;
    }
    const float sc = exp2f((float)(-ksc));
    #pragma unroll
    for (int k = 0; k < 64; ++k) brow[k] *= sc;

    // init Q = I + B/8 (folds first Horner step; order 8 total)
    {
        const float i8 = 1.0f / 8.0f;
        #pragma unroll
        for (int t = 0; t < 8; ++t) {
            int c = c0 + 4 * t;
            float4 o4 = make_float4(
                brow[c+0] * i8 + ((c+0 == i) ? 1.f : 0.f),
                brow[c+1] * i8 + ((c+1 == i) ? 1.f : 0.f),
                brow[c+2] * i8 + ((c+2 == i) ? 1.f : 0.f),
                brow[c+3] * i8 + ((c+3 == i) ? 1.f : 0.f));
            *(float4*)&Q[i * DQ + c] = o4;
        }
    }
    __syncthreads();

    float rrow[32];

    // Horner: Q_{n-1} = I + (B * Q_n)/n, n = 7..1
    for (int n = 7; n >= 1; --n) {
        #pragma unroll
        for (int j = 0; j < 32; ++j) rrow[j] = 0.0f;
        for (int k = 0; k < D; ++k) {
            float bv = brow[k];
            #pragma unroll
            for (int t = 0; t < 8; ++t) {
                float4 q = *(const float4*)&Q[k * DQ + c0 + 4 * t];
                rrow[4*t+0] = fmaf(bv, q.x, rrow[4*t+0]);
                rrow[4*t+1] = fmaf(bv, q.y, rrow[4*t+1]);
                rrow[4*t+2] = fmaf(bv, q.z, rrow[4*t+2]);
                rrow[4*t+3] = fmaf(bv, q.w, rrow[4*t+3]);
            }
        }
        __syncthreads();
        const float invn = 1.0f / (float)n;
        #pragma unroll
        for (int t = 0; t < 8; ++t) {
            int c = c0 + 4 * t;
            float4 o4 = make_float4(
                rrow[4*t+0] * invn + ((c+0 == i) ? 1.f : 0.f),
                rrow[4*t+1] * invn + ((c+1 == i) ? 1.f : 0.f),
                rrow[4*t+2] * invn + ((c+2 == i) ? 1.f : 0.f),
                rrow[4*t+3] * invn + ((c+3 == i) ? 1.f : 0.f));
            *(float4*)&Q[i * DQ + c] = o4;
        }
        __syncthreads();
    }

    // repeated squaring (ksc uniform across the block)
    for (int t2 = 0; t2 < ksc; ++t2) {
        #pragma unroll
        for (int t = 0; t < 16; ++t) {
            float4 v = *(const float4*)&Q[i * DQ + 4 * t];
            brow[4*t+0] = v.x; brow[4*t+1] = v.y; brow[4*t+2] = v.z; brow[4*t+3] = v.w;
        }
        #pragma unroll
        for (int j = 0; j < 32; ++j) rrow[j] = 0.0f;
        for (int k = 0; k < D; ++k) {
            float bv = brow[k];
            #pragma unroll
            for (int t = 0; t < 8; ++t) {
                float4 q = *(const float4*)&Q[k * DQ + c0 + 4 * t];
                rrow[4*t+0] = fmaf(bv, q.x, rrow[4*t+0]);
                rrow[4*t+1] = fmaf(bv, q.y, rrow[4*t+1]);
                rrow[4*t+2] = fmaf(bv, q.z, rrow[4*t+2]);
                rrow[4*t+3] = fmaf(bv, q.w, rrow[4*t+3]);
            }
        }
        __syncthreads();
        #pragma unroll
        for (int t = 0; t < 8; ++t)
            *(float4*)&Q[i * DQ + c0 + 4 * t] =
                make_float4(rrow[4*t+0], rrow[4*t+1], rrow[4*t+2], rrow[4*t+3]);
        __syncthreads();
    }

    float* om = out + (size_t)m * DD + i * D + c0;
    #pragma unroll
    for (int t = 0; t < 8; ++t) {
        float4 v = *(const float4*)&Q[i * DQ + c0 + 4 * t];
        *(float4*)&om[4 * t] = v;
    }
}

// ========================================================================
extern "C" void kernel_launch(void* const* d_in, const int* in_sizes, int n_in,
                              void* d_out, int out_size) {
    const float* X  = (const float*)d_in[0];
    const float* bw = (const float*)d_in[1];
    float* out = (float*)d_out;

    onesided_log_kernel<<<NMAT / 2, 128>>>(X);
    gram_kernel<<<dim3(4, 4, 8), 256>>>();
    w_kernel<<<NMAT, 256>>>(bw);
    colsum_kernel<<<8, 256>>>();
    ms_kernel<<<dim3(64, 4), 256>>>();
    expm_kernel<<<NMAT, 128>>>(out);
}